// round 2
// baseline (speedup 1.0000x reference)
#include <cuda_runtime.h>
#include <cuda_bf16.h>
#include <math.h>

// Problem constants (dataset-fixed)
#define MAX_NODES 50000
#define FEAT 128

// Scratch (allocation-free rule: device globals)
__device__ float g_agg[MAX_NODES * FEAT];
__device__ float g_deg[MAX_NODES];

// ---------------------------------------------------------------------------
// Kernel 1: zero the accumulators
// ---------------------------------------------------------------------------
__global__ void zero_kernel(float* __restrict__ agg, float* __restrict__ deg,
                            int n_agg4, int n_deg) {
    int i = blockIdx.x * blockDim.x + threadIdx.x;
    if (i < n_agg4) {
        ((float4*)agg)[i] = make_float4(0.f, 0.f, 0.f, 0.f);
    }
    if (i < n_deg) {
        deg[i] = 0.f;
    }
}

// ---------------------------------------------------------------------------
// Kernel 2: edge gather-scale-scatter. One warp per edge.
// Each lane handles one float4 (4 feats): 32 lanes * 4 = 128 feats.
// Scatter via red.global.add.v4.f32 (16B L2 reduction, no return).
// NOTE: edge_index arrives as int32 (JAX x64-disabled downcasts int64).
// ---------------------------------------------------------------------------
__global__ void edge_kernel(const float* __restrict__ x,
                            const int* __restrict__ ei,
                            const float* __restrict__ elen,
                            const float* __restrict__ log_scale_p,
                            const float* __restrict__ fw_p,
                            const float* __restrict__ fb_p,
                            float* __restrict__ agg,
                            float* __restrict__ deg,
                            int E, int n_nodes) {
    int gtid = blockIdx.x * blockDim.x + threadIdx.x;
    int e    = gtid >> 5;
    int lane = gtid & 31;
    if (e >= E) return;

    int s = ei[e];          // sender
    int r = ei[E + e];      // receiver
    // defensive clamp (branch-free); indices are expected in-range
    s = min(max(s, 0), n_nodes - 1);
    r = min(max(r, 0), n_nodes - 1);
    float len = elen[e];

    float scale = expf(log_scale_p[0]);
    float t = fmaxf(len / (scale + 1e-6f), 0.f);
    float d = expf(-t * t);
    float g = 1.f / (1.f + expf(-(len * fw_p[0] + fb_p[0])));
    float w = d * g;
    // nan_to_num: nan compares false; clamp non-finite to 0
    if (!(w > -3.0e38f && w < 3.0e38f)) w = 0.f;

    float4 v = ((const float4*)(x + (size_t)s * FEAT))[lane];
    float4 m = make_float4(v.x * w, v.y * w, v.z * w, v.w * w);

    float* dst = agg + (size_t)r * FEAT + lane * 4;
    asm volatile("red.global.add.v4.f32 [%0], {%1, %2, %3, %4};"
                 :: "l"(dst), "f"(m.x), "f"(m.y), "f"(m.z), "f"(m.w)
                 : "memory");
    if (lane == 0) {
        atomicAdd(deg + r, 1.0f);  // no return use -> REDG
    }
}

// ---------------------------------------------------------------------------
// Kernel 3: out = x + (agg / max(deg,1)) @ W_mix
// Block: 256 threads, BM=64 rows. W (64KB) + A tile (32KB) in dynamic smem.
// Thread (tx = tid&31 -> col*4, ty = tid>>5 -> 8 rows): 8x4 register tile.
// ---------------------------------------------------------------------------
#define BM 64

__global__ void gemm_kernel(const float* __restrict__ x,
                            const float* __restrict__ W,
                            const float* __restrict__ agg,
                            const float* __restrict__ deg,
                            float* __restrict__ out,
                            int n_nodes) {
    extern __shared__ float sm[];
    float* Ws = sm;                  // 128*128
    float* As = sm + FEAT * FEAT;    // BM*128

    int tid = threadIdx.x;
    int row0 = blockIdx.x * BM;

    // Load W_mix into smem (float4, coalesced)
    for (int i = tid; i < FEAT * FEAT / 4; i += 256) {
        ((float4*)Ws)[i] = ((const float4*)W)[i];
    }
    // Load A tile = agg / max(deg,1); zero-pad out-of-range rows
    for (int i = tid; i < BM * FEAT / 4; i += 256) {
        int r = i / (FEAT / 4);
        int c = i % (FEAT / 4);
        int row = row0 + r;
        float4 v = make_float4(0.f, 0.f, 0.f, 0.f);
        if (row < n_nodes) {
            v = ((const float4*)(agg + (size_t)row * FEAT))[c];
            float inv = 1.0f / fmaxf(deg[row], 1.0f);
            v.x *= inv; v.y *= inv; v.z *= inv; v.w *= inv;
        }
        ((float4*)(As + r * FEAT))[c] = v;
    }
    __syncthreads();

    int tx = tid & 31;   // column group: cols [tx*4, tx*4+3]
    int ty = tid >> 5;   // row group: rows [ty*8, ty*8+7]

    float acc[8][4];
#pragma unroll
    for (int r = 0; r < 8; r++)
#pragma unroll
        for (int c = 0; c < 4; c++) acc[r][c] = 0.f;

#pragma unroll 4
    for (int k = 0; k < FEAT; k++) {
        float4 w = ((const float4*)(Ws + k * FEAT))[tx];
#pragma unroll
        for (int r = 0; r < 8; r++) {
            float a = As[(ty * 8 + r) * FEAT + k];   // warp-broadcast
            acc[r][0] = fmaf(a, w.x, acc[r][0]);
            acc[r][1] = fmaf(a, w.y, acc[r][1]);
            acc[r][2] = fmaf(a, w.z, acc[r][2]);
            acc[r][3] = fmaf(a, w.w, acc[r][3]);
        }
    }

#pragma unroll
    for (int r = 0; r < 8; r++) {
        int row = row0 + ty * 8 + r;
        if (row < n_nodes) {
            float4 xv = ((const float4*)(x + (size_t)row * FEAT))[tx];
            float4 o = make_float4(acc[r][0] + xv.x, acc[r][1] + xv.y,
                                   acc[r][2] + xv.z, acc[r][3] + xv.w);
            ((float4*)(out + (size_t)row * FEAT))[tx] = o;
        }
    }
}

// ---------------------------------------------------------------------------
extern "C" void kernel_launch(void* const* d_in, const int* in_sizes, int n_in,
                              void* d_out, int out_size) {
    const float* x    = (const float*)d_in[0];
    const int*   ei   = (const int*)d_in[1];
    const float* elen = (const float*)d_in[2];
    const float* W    = (const float*)d_in[3];
    const float* lsc  = (const float*)d_in[4];
    const float* fw   = (const float*)d_in[5];
    const float* fb   = (const float*)d_in[6];
    float* out = (float*)d_out;

    int n_nodes = in_sizes[0] / FEAT;
    int E       = in_sizes[2];

    float* agg;
    float* deg;
    cudaGetSymbolAddress((void**)&agg, g_agg);
    cudaGetSymbolAddress((void**)&deg, g_deg);

    // 1. zero scratch
    {
        int n_agg4 = n_nodes * FEAT / 4;
        int threads = 256;
        int blocks = (n_agg4 + threads - 1) / threads;
        zero_kernel<<<blocks, threads>>>(agg, deg, n_agg4, n_nodes);
    }

    // 2. edge scatter
    {
        long long total_threads = (long long)E * 32;
        int threads = 256;
        int blocks = (int)((total_threads + threads - 1) / threads);
        edge_kernel<<<blocks, threads>>>(x, ei, elen, lsc, fw, fb, agg, deg,
                                         E, n_nodes);
    }

    // 3. fused normalize + GEMM + residual
    {
        int smem = (FEAT * FEAT + BM * FEAT) * (int)sizeof(float);  // 96 KB
        cudaFuncSetAttribute(gemm_kernel,
                             cudaFuncAttributeMaxDynamicSharedMemorySize, smem);
        int blocks = (n_nodes + BM - 1) / BM;
        gemm_kernel<<<blocks, 256, smem>>>(x, W, agg, deg, out, n_nodes);
    }
}

// round 3
// speedup vs baseline: 1.1820x; 1.1820x over previous
#include <cuda_runtime.h>
#include <cuda_bf16.h>
#include <math.h>

#define MAX_NODES 50000
#define MAX_EDGES 1500000
#define FEAT 128

// Scratch (device globals; allocation-free rule)
__device__ float g_agg[MAX_NODES * FEAT];
__device__ int   g_deg[MAX_NODES];
__device__ int   g_rowstart[MAX_NODES];
__device__ int   g_writeptr[MAX_NODES];
__device__ uint2 g_rec[MAX_EDGES];   // {sender, weight-bits}

// ---------------------------------------------------------------------------
// 1) zero the degree counters
// ---------------------------------------------------------------------------
__global__ void zero_kernel(int* __restrict__ deg, int n) {
    int i = blockIdx.x * blockDim.x + threadIdx.x;
    if (i < n) deg[i] = 0;
}

// ---------------------------------------------------------------------------
// 2) histogram of receivers (also the degree used for normalization)
// ---------------------------------------------------------------------------
__global__ void hist_kernel(const int* __restrict__ ei, int* __restrict__ deg,
                            int E, int n_nodes) {
    int e = blockIdx.x * blockDim.x + threadIdx.x;
    if (e >= E) return;
    int r = ei[E + e];
    r = min(max(r, 0), n_nodes - 1);
    atomicAdd(deg + r, 1);           // no return use -> REDG
}

// ---------------------------------------------------------------------------
// 3) exclusive prefix scan over 50K counts (single block, 1024 threads)
//    writes row_start[] and writeptr[]
// ---------------------------------------------------------------------------
__global__ void scan_kernel(const int* __restrict__ deg,
                            int* __restrict__ rowstart,
                            int* __restrict__ writeptr, int n) {
    __shared__ int ssum[1024];
    int t = threadIdx.x;
    int chunk = (n + 1023) / 1024;
    int lo = t * chunk;
    int hi = min(n, lo + chunk);

    int local = 0;
    for (int i = lo; i < hi; i++) local += deg[i];

    ssum[t] = local;
    __syncthreads();
    // Hillis-Steele inclusive scan
    for (int off = 1; off < 1024; off <<= 1) {
        int v = (t >= off) ? ssum[t - off] : 0;
        __syncthreads();
        ssum[t] += v;
        __syncthreads();
    }
    int start = ssum[t] - local;   // exclusive prefix of this thread's chunk

    for (int i = lo; i < hi; i++) {
        rowstart[i] = start;
        writeptr[i] = start;
        start += deg[i];
    }
}

// ---------------------------------------------------------------------------
// 4) scatter edges into receiver buckets, computing the edge weight
// ---------------------------------------------------------------------------
__global__ void scatter_kernel(const int* __restrict__ ei,
                               const float* __restrict__ elen,
                               const float* __restrict__ log_scale_p,
                               const float* __restrict__ fw_p,
                               const float* __restrict__ fb_p,
                               int* __restrict__ writeptr,
                               uint2* __restrict__ rec,
                               int E, int n_nodes) {
    int e = blockIdx.x * blockDim.x + threadIdx.x;
    if (e >= E) return;
    int s = ei[e];
    int r = ei[E + e];
    s = min(max(s, 0), n_nodes - 1);
    r = min(max(r, 0), n_nodes - 1);
    float len = elen[e];

    float scale = expf(log_scale_p[0]);
    float t = fmaxf(len / (scale + 1e-6f), 0.f);
    float d = expf(-t * t);
    float g = 1.f / (1.f + expf(-(len * fw_p[0] + fb_p[0])));
    float w = d * g;
    if (!(w > -3.0e38f && w < 3.0e38f)) w = 0.f;  // nan_to_num

    int pos = atomicAdd(writeptr + r, 1);
    rec[pos] = make_uint2((unsigned)s, __float_as_uint(w));
}

// ---------------------------------------------------------------------------
// 5) race-free gather: one warp per receiver node. Coalesced record load +
//    shfl broadcast; 4-edge unroll for MLP on the x-row gathers.
//    Writes normalized agg (deg division folded in).
// ---------------------------------------------------------------------------
__global__ void gather_kernel(const float* __restrict__ x,
                              const uint2* __restrict__ rec,
                              const int* __restrict__ rowstart,
                              const int* __restrict__ deg,
                              float* __restrict__ agg, int n_nodes) {
    int wid  = (blockIdx.x * blockDim.x + threadIdx.x) >> 5;
    int lane = threadIdx.x & 31;
    if (wid >= n_nodes) return;

    int base = rowstart[wid];
    int d    = deg[wid];
    float4 acc = make_float4(0.f, 0.f, 0.f, 0.f);

    for (int j0 = 0; j0 < d; j0 += 32) {
        int n = min(32, d - j0);
        uint2 rv = make_uint2(0u, 0u);
        if (lane < n) rv = rec[base + j0 + lane];

        int k = 0;
        for (; k + 4 <= n; k += 4) {
            int   s0 = __shfl_sync(0xffffffffu, (int)rv.x, k);
            int   s1 = __shfl_sync(0xffffffffu, (int)rv.x, k + 1);
            int   s2 = __shfl_sync(0xffffffffu, (int)rv.x, k + 2);
            int   s3 = __shfl_sync(0xffffffffu, (int)rv.x, k + 3);
            float w0 = __uint_as_float(__shfl_sync(0xffffffffu, rv.y, k));
            float w1 = __uint_as_float(__shfl_sync(0xffffffffu, rv.y, k + 1));
            float w2 = __uint_as_float(__shfl_sync(0xffffffffu, rv.y, k + 2));
            float w3 = __uint_as_float(__shfl_sync(0xffffffffu, rv.y, k + 3));

            float4 v0 = ((const float4*)(x + (size_t)s0 * FEAT))[lane];
            float4 v1 = ((const float4*)(x + (size_t)s1 * FEAT))[lane];
            float4 v2 = ((const float4*)(x + (size_t)s2 * FEAT))[lane];
            float4 v3 = ((const float4*)(x + (size_t)s3 * FEAT))[lane];

            acc.x = fmaf(w0, v0.x, acc.x); acc.y = fmaf(w0, v0.y, acc.y);
            acc.z = fmaf(w0, v0.z, acc.z); acc.w = fmaf(w0, v0.w, acc.w);
            acc.x = fmaf(w1, v1.x, acc.x); acc.y = fmaf(w1, v1.y, acc.y);
            acc.z = fmaf(w1, v1.z, acc.z); acc.w = fmaf(w1, v1.w, acc.w);
            acc.x = fmaf(w2, v2.x, acc.x); acc.y = fmaf(w2, v2.y, acc.y);
            acc.z = fmaf(w2, v2.z, acc.z); acc.w = fmaf(w2, v2.w, acc.w);
            acc.x = fmaf(w3, v3.x, acc.x); acc.y = fmaf(w3, v3.y, acc.y);
            acc.z = fmaf(w3, v3.z, acc.z); acc.w = fmaf(w3, v3.w, acc.w);
        }
        for (; k < n; k++) {
            int   s0 = __shfl_sync(0xffffffffu, (int)rv.x, k);
            float w0 = __uint_as_float(__shfl_sync(0xffffffffu, rv.y, k));
            float4 v0 = ((const float4*)(x + (size_t)s0 * FEAT))[lane];
            acc.x = fmaf(w0, v0.x, acc.x); acc.y = fmaf(w0, v0.y, acc.y);
            acc.z = fmaf(w0, v0.z, acc.z); acc.w = fmaf(w0, v0.w, acc.w);
        }
    }

    float inv = 1.f / fmaxf((float)d, 1.f);
    ((float4*)(agg + (size_t)wid * FEAT))[lane] =
        make_float4(acc.x * inv, acc.y * inv, acc.z * inv, acc.w * inv);
}

// ---------------------------------------------------------------------------
// 6) out = x + agg @ W_mix   (agg already normalized)
// ---------------------------------------------------------------------------
#define BM 64

__global__ void gemm_kernel(const float* __restrict__ x,
                            const float* __restrict__ W,
                            const float* __restrict__ agg,
                            float* __restrict__ out,
                            int n_nodes) {
    extern __shared__ float sm[];
    float* Ws = sm;                  // 128*128
    float* As = sm + FEAT * FEAT;    // BM*128

    int tid = threadIdx.x;
    int row0 = blockIdx.x * BM;

    for (int i = tid; i < FEAT * FEAT / 4; i += 256) {
        ((float4*)Ws)[i] = ((const float4*)W)[i];
    }
    for (int i = tid; i < BM * FEAT / 4; i += 256) {
        int r = i / (FEAT / 4);
        int c = i % (FEAT / 4);
        int row = row0 + r;
        float4 v = make_float4(0.f, 0.f, 0.f, 0.f);
        if (row < n_nodes) {
            v = ((const float4*)(agg + (size_t)row * FEAT))[c];
        }
        ((float4*)(As + r * FEAT))[c] = v;
    }
    __syncthreads();

    int tx = tid & 31;
    int ty = tid >> 5;

    float acc[8][4];
#pragma unroll
    for (int r = 0; r < 8; r++)
#pragma unroll
        for (int c = 0; c < 4; c++) acc[r][c] = 0.f;

#pragma unroll 4
    for (int k = 0; k < FEAT; k++) {
        float4 w = ((const float4*)(Ws + k * FEAT))[tx];
#pragma unroll
        for (int r = 0; r < 8; r++) {
            float a = As[(ty * 8 + r) * FEAT + k];
            acc[r][0] = fmaf(a, w.x, acc[r][0]);
            acc[r][1] = fmaf(a, w.y, acc[r][1]);
            acc[r][2] = fmaf(a, w.z, acc[r][2]);
            acc[r][3] = fmaf(a, w.w, acc[r][3]);
        }
    }

#pragma unroll
    for (int r = 0; r < 8; r++) {
        int row = row0 + ty * 8 + r;
        if (row < n_nodes) {
            float4 xv = ((const float4*)(x + (size_t)row * FEAT))[tx];
            float4 o = make_float4(acc[r][0] + xv.x, acc[r][1] + xv.y,
                                   acc[r][2] + xv.z, acc[r][3] + xv.w);
            ((float4*)(out + (size_t)row * FEAT))[tx] = o;
        }
    }
}

// ---------------------------------------------------------------------------
extern "C" void kernel_launch(void* const* d_in, const int* in_sizes, int n_in,
                              void* d_out, int out_size) {
    const float* x    = (const float*)d_in[0];
    const int*   ei   = (const int*)d_in[1];
    const float* elen = (const float*)d_in[2];
    const float* W    = (const float*)d_in[3];
    const float* lsc  = (const float*)d_in[4];
    const float* fw   = (const float*)d_in[5];
    const float* fb   = (const float*)d_in[6];
    float* out = (float*)d_out;

    int n_nodes = in_sizes[0] / FEAT;
    int E       = in_sizes[2];
    if (E > MAX_EDGES) E = MAX_EDGES;

    float* agg;      cudaGetSymbolAddress((void**)&agg, g_agg);
    int*   deg;      cudaGetSymbolAddress((void**)&deg, g_deg);
    int*   rowstart; cudaGetSymbolAddress((void**)&rowstart, g_rowstart);
    int*   writeptr; cudaGetSymbolAddress((void**)&writeptr, g_writeptr);
    uint2* rec;      cudaGetSymbolAddress((void**)&rec, g_rec);

    // 1) zero degree counters
    zero_kernel<<<(n_nodes + 255) / 256, 256>>>(deg, n_nodes);

    // 2) receiver histogram
    hist_kernel<<<(E + 255) / 256, 256>>>(ei, deg, E, n_nodes);

    // 3) prefix scan -> rowstart / writeptr
    scan_kernel<<<1, 1024>>>(deg, rowstart, writeptr, n_nodes);

    // 4) bucket scatter with weight computation
    scatter_kernel<<<(E + 255) / 256, 256>>>(ei, elen, lsc, fw, fb,
                                             writeptr, rec, E, n_nodes);

    // 5) race-free per-node gather (warp per node)
    {
        long long total = (long long)n_nodes * 32;
        int blocks = (int)((total + 255) / 256);
        gather_kernel<<<blocks, 256>>>(x, rec, rowstart, deg, agg, n_nodes);
    }

    // 6) GEMM + residual
    {
        int smem = (FEAT * FEAT + BM * FEAT) * (int)sizeof(float);  // 96 KB
        cudaFuncSetAttribute(gemm_kernel,
                             cudaFuncAttributeMaxDynamicSharedMemorySize, smem);
        gemm_kernel<<<(n_nodes + BM - 1) / BM, 256, smem>>>(x, W, agg, out,
                                                            n_nodes);
    }
}

// round 4
// speedup vs baseline: 1.2047x; 1.0192x over previous
#include <cuda_runtime.h>
#include <cuda_bf16.h>
#include <math.h>

#define MAX_NODES 50000
#define MAX_EDGES 1500000
#define FEAT 128

// Scratch (device globals; allocation-free rule)
__device__ float g_agg[MAX_NODES * FEAT];
__device__ int   g_deg[MAX_NODES];
__device__ int   g_rowstart[MAX_NODES];
__device__ int   g_writeptr[MAX_NODES];
__device__ uint2 g_rec[MAX_EDGES];   // {sender, weight-bits}

// ---------------------------------------------------------------------------
// 1) zero the degree counters
// ---------------------------------------------------------------------------
__global__ void zero_kernel(int* __restrict__ deg, int n) {
    int i = blockIdx.x * blockDim.x + threadIdx.x;
    if (i < n) deg[i] = 0;
}

// ---------------------------------------------------------------------------
// 2) histogram of receivers (also the degree used for normalization)
// ---------------------------------------------------------------------------
__global__ void hist_kernel(const int* __restrict__ ei, int* __restrict__ deg,
                            int E, int n_nodes) {
    int e = blockIdx.x * blockDim.x + threadIdx.x;
    if (e >= E) return;
    int r = ei[E + e];
    r = min(max(r, 0), n_nodes - 1);
    atomicAdd(deg + r, 1);           // no return use -> REDG
}

// ---------------------------------------------------------------------------
// 3) exclusive prefix scan over 50K counts (single block, 1024 threads)
// ---------------------------------------------------------------------------
__global__ void scan_kernel(const int* __restrict__ deg,
                            int* __restrict__ rowstart,
                            int* __restrict__ writeptr, int n) {
    __shared__ int ssum[1024];
    int t = threadIdx.x;
    int chunk = (n + 1023) / 1024;   // 49 for n=50000
    int lo = t * chunk;
    int hi = min(n, lo + chunk);

    int local = 0;
    for (int i = lo; i < hi; i++) local += deg[i];

    ssum[t] = local;
    __syncthreads();
    // Hillis-Steele inclusive scan
    for (int off = 1; off < 1024; off <<= 1) {
        int v = (t >= off) ? ssum[t - off] : 0;
        __syncthreads();
        ssum[t] += v;
        __syncthreads();
    }
    int start = ssum[t] - local;   // exclusive prefix of this thread's chunk

    for (int i = lo; i < hi; i++) {
        rowstart[i] = start;
        writeptr[i] = start;
        start += deg[i];
    }
}

// ---------------------------------------------------------------------------
// 4) scatter edges into receiver buckets, computing the edge weight
// ---------------------------------------------------------------------------
__global__ void scatter_kernel(const int* __restrict__ ei,
                               const float* __restrict__ elen,
                               const float* __restrict__ log_scale_p,
                               const float* __restrict__ fw_p,
                               const float* __restrict__ fb_p,
                               int* __restrict__ writeptr,
                               uint2* __restrict__ rec,
                               int E, int n_nodes) {
    int e = blockIdx.x * blockDim.x + threadIdx.x;
    if (e >= E) return;
    int s = ei[e];
    int r = ei[E + e];
    s = min(max(s, 0), n_nodes - 1);
    r = min(max(r, 0), n_nodes - 1);
    float len = elen[e];

    float scale = expf(log_scale_p[0]);
    float t = fmaxf(len / (scale + 1e-6f), 0.f);
    float d = expf(-t * t);
    float g = 1.f / (1.f + expf(-(len * fw_p[0] + fb_p[0])));
    float w = d * g;
    if (!(w > -3.0e38f && w < 3.0e38f)) w = 0.f;  // nan_to_num

    int pos = atomicAdd(writeptr + r, 1);
    rec[pos] = make_uint2((unsigned)s, __float_as_uint(w));
}

// ---------------------------------------------------------------------------
// 5) race-free gather: one warp per receiver node. Coalesced record load +
//    shfl broadcast; 8-edge unroll: all 8 row-gathers issued back-to-back
//    (MLP=8) before consumption. Writes normalized agg.
// ---------------------------------------------------------------------------
__global__ void gather_kernel(const float* __restrict__ x,
                              const uint2* __restrict__ rec,
                              const int* __restrict__ rowstart,
                              const int* __restrict__ deg,
                              float* __restrict__ agg, int n_nodes) {
    int wid  = (blockIdx.x * blockDim.x + threadIdx.x) >> 5;
    int lane = threadIdx.x & 31;
    if (wid >= n_nodes) return;

    int base = rowstart[wid];
    int d    = deg[wid];
    float4 acc = make_float4(0.f, 0.f, 0.f, 0.f);

    for (int j0 = 0; j0 < d; j0 += 32) {
        int n = min(32, d - j0);
        uint2 rv = make_uint2(0u, 0u);
        if (lane < n) rv = rec[base + j0 + lane];

        int k = 0;
        for (; k + 8 <= n; k += 8) {
            int   si[8];
            float wi[8];
#pragma unroll
            for (int u = 0; u < 8; u++) {
                si[u] = __shfl_sync(0xffffffffu, (int)rv.x, k + u);
                wi[u] = __uint_as_float(__shfl_sync(0xffffffffu, rv.y, k + u));
            }
            float4 v[8];
#pragma unroll
            for (int u = 0; u < 8; u++) {
                v[u] = ((const float4*)(x + (size_t)si[u] * FEAT))[lane];
            }
#pragma unroll
            for (int u = 0; u < 8; u++) {
                acc.x = fmaf(wi[u], v[u].x, acc.x);
                acc.y = fmaf(wi[u], v[u].y, acc.y);
                acc.z = fmaf(wi[u], v[u].z, acc.z);
                acc.w = fmaf(wi[u], v[u].w, acc.w);
            }
        }
        if (k + 4 <= n) {
            int   si[4];
            float wi[4];
#pragma unroll
            for (int u = 0; u < 4; u++) {
                si[u] = __shfl_sync(0xffffffffu, (int)rv.x, k + u);
                wi[u] = __uint_as_float(__shfl_sync(0xffffffffu, rv.y, k + u));
            }
            float4 v[4];
#pragma unroll
            for (int u = 0; u < 4; u++) {
                v[u] = ((const float4*)(x + (size_t)si[u] * FEAT))[lane];
            }
#pragma unroll
            for (int u = 0; u < 4; u++) {
                acc.x = fmaf(wi[u], v[u].x, acc.x);
                acc.y = fmaf(wi[u], v[u].y, acc.y);
                acc.z = fmaf(wi[u], v[u].z, acc.z);
                acc.w = fmaf(wi[u], v[u].w, acc.w);
            }
            k += 4;
        }
        for (; k < n; k++) {
            int   s0 = __shfl_sync(0xffffffffu, (int)rv.x, k);
            float w0 = __uint_as_float(__shfl_sync(0xffffffffu, rv.y, k));
            float4 v0 = ((const float4*)(x + (size_t)s0 * FEAT))[lane];
            acc.x = fmaf(w0, v0.x, acc.x); acc.y = fmaf(w0, v0.y, acc.y);
            acc.z = fmaf(w0, v0.z, acc.z); acc.w = fmaf(w0, v0.w, acc.w);
        }
    }

    float inv = 1.f / fmaxf((float)d, 1.f);
    ((float4*)(agg + (size_t)wid * FEAT))[lane] =
        make_float4(acc.x * inv, acc.y * inv, acc.z * inv, acc.w * inv);
}

// ---------------------------------------------------------------------------
// 6) out = x + agg @ W_mix   (agg already normalized)
// ---------------------------------------------------------------------------
#define BM 64

__global__ void gemm_kernel(const float* __restrict__ x,
                            const float* __restrict__ W,
                            const float* __restrict__ agg,
                            float* __restrict__ out,
                            int n_nodes) {
    extern __shared__ float sm[];
    float* Ws = sm;                  // 128*128
    float* As = sm + FEAT * FEAT;    // BM*128

    int tid = threadIdx.x;
    int row0 = blockIdx.x * BM;

    for (int i = tid; i < FEAT * FEAT / 4; i += 256) {
        ((float4*)Ws)[i] = ((const float4*)W)[i];
    }
    for (int i = tid; i < BM * FEAT / 4; i += 256) {
        int r = i / (FEAT / 4);
        int c = i % (FEAT / 4);
        int row = row0 + r;
        float4 v = make_float4(0.f, 0.f, 0.f, 0.f);
        if (row < n_nodes) {
            v = ((const float4*)(agg + (size_t)row * FEAT))[c];
        }
        ((float4*)(As + r * FEAT))[c] = v;
    }
    __syncthreads();

    int tx = tid & 31;
    int ty = tid >> 5;

    float acc[8][4];
#pragma unroll
    for (int r = 0; r < 8; r++)
#pragma unroll
        for (int c = 0; c < 4; c++) acc[r][c] = 0.f;

#pragma unroll 4
    for (int k = 0; k < FEAT; k++) {
        float4 w = ((const float4*)(Ws + k * FEAT))[tx];
#pragma unroll
        for (int r = 0; r < 8; r++) {
            float a = As[(ty * 8 + r) * FEAT + k];
            acc[r][0] = fmaf(a, w.x, acc[r][0]);
            acc[r][1] = fmaf(a, w.y, acc[r][1]);
            acc[r][2] = fmaf(a, w.z, acc[r][2]);
            acc[r][3] = fmaf(a, w.w, acc[r][3]);
        }
    }

#pragma unroll
    for (int r = 0; r < 8; r++) {
        int row = row0 + ty * 8 + r;
        if (row < n_nodes) {
            float4 xv = ((const float4*)(x + (size_t)row * FEAT))[tx];
            float4 o = make_float4(acc[r][0] + xv.x, acc[r][1] + xv.y,
                                   acc[r][2] + xv.z, acc[r][3] + xv.w);
            ((float4*)(out + (size_t)row * FEAT))[tx] = o;
        }
    }
}

// ---------------------------------------------------------------------------
extern "C" void kernel_launch(void* const* d_in, const int* in_sizes, int n_in,
                              void* d_out, int out_size) {
    const float* x    = (const float*)d_in[0];
    const int*   ei   = (const int*)d_in[1];
    const float* elen = (const float*)d_in[2];
    const float* W    = (const float*)d_in[3];
    const float* lsc  = (const float*)d_in[4];
    const float* fw   = (const float*)d_in[5];
    const float* fb   = (const float*)d_in[6];
    float* out = (float*)d_out;

    int n_nodes = in_sizes[0] / FEAT;
    int E       = in_sizes[2];
    if (E > MAX_EDGES) E = MAX_EDGES;

    float* agg;      cudaGetSymbolAddress((void**)&agg, g_agg);
    int*   deg;      cudaGetSymbolAddress((void**)&deg, g_deg);
    int*   rowstart; cudaGetSymbolAddress((void**)&rowstart, g_rowstart);
    int*   writeptr; cudaGetSymbolAddress((void**)&writeptr, g_writeptr);
    uint2* rec;      cudaGetSymbolAddress((void**)&rec, g_rec);

    // 1) zero degree counters
    zero_kernel<<<(n_nodes + 255) / 256, 256>>>(deg, n_nodes);

    // 2) receiver histogram
    hist_kernel<<<(E + 255) / 256, 256>>>(ei, deg, E, n_nodes);

    // 3) prefix scan -> rowstart / writeptr
    scan_kernel<<<1, 1024>>>(deg, rowstart, writeptr, n_nodes);

    // 4) bucket scatter with weight computation
    scatter_kernel<<<(E + 255) / 256, 256>>>(ei, elen, lsc, fw, fb,
                                             writeptr, rec, E, n_nodes);

    // 5) race-free per-node gather (warp per node)
    {
        long long total = (long long)n_nodes * 32;
        int blocks = (int)((total + 255) / 256);
        gather_kernel<<<blocks, 256>>>(x, rec, rowstart, deg, agg, n_nodes);
    }

    // 6) GEMM + residual
    {
        int smem = (FEAT * FEAT + BM * FEAT) * (int)sizeof(float);  // 96 KB
        cudaFuncSetAttribute(gemm_kernel,
                             cudaFuncAttributeMaxDynamicSharedMemorySize, smem);
        gemm_kernel<<<(n_nodes + BM - 1) / BM, 256, smem>>>(x, W, agg, out,
                                                            n_nodes);
    }
}

// round 5
// speedup vs baseline: 1.5874x; 1.3177x over previous
#include <cuda_runtime.h>
#include <cuda_fp16.h>
#include <math.h>

#define MAX_NODES 50000
#define MAX_EDGES 1500000
#define FEAT 128

// Scratch (device globals; allocation-free rule)
__device__ float  g_agg[MAX_NODES * FEAT];
__device__ __half g_xh[MAX_NODES * FEAT];     // fp16 copy of x
__device__ int    g_deg[MAX_NODES];
__device__ int    g_rowstart[MAX_NODES];
__device__ int    g_writeptr[MAX_NODES];
__device__ uint2  g_rec[MAX_EDGES];           // {sender, weight-bits}

// ---------------------------------------------------------------------------
// 0) convert x -> fp16 (8 floats -> 8 halves per thread, 16B stores)
// ---------------------------------------------------------------------------
__global__ void convert_kernel(const float* __restrict__ x,
                               __half* __restrict__ xh, int n8) {
    int i = blockIdx.x * blockDim.x + threadIdx.x;
    if (i >= n8) return;
    const float4* x4 = (const float4*)x;
    float4 a = x4[2 * i];
    float4 b = x4[2 * i + 1];
    __half2 h0 = __floats2half2_rn(a.x, a.y);
    __half2 h1 = __floats2half2_rn(a.z, a.w);
    __half2 h2 = __floats2half2_rn(b.x, b.y);
    __half2 h3 = __floats2half2_rn(b.z, b.w);
    uint4 o;
    o.x = *(unsigned*)&h0; o.y = *(unsigned*)&h1;
    o.z = *(unsigned*)&h2; o.w = *(unsigned*)&h3;
    ((uint4*)xh)[i] = o;
}

// ---------------------------------------------------------------------------
// 1) zero the degree counters
// ---------------------------------------------------------------------------
__global__ void zero_kernel(int* __restrict__ deg, int n) {
    int i = blockIdx.x * blockDim.x + threadIdx.x;
    if (i < n) deg[i] = 0;
}

// ---------------------------------------------------------------------------
// 2) histogram of receivers
// ---------------------------------------------------------------------------
__global__ void hist_kernel(const int* __restrict__ ei, int* __restrict__ deg,
                            int E, int n_nodes) {
    int e = blockIdx.x * blockDim.x + threadIdx.x;
    if (e >= E) return;
    int r = ei[E + e];
    r = min(max(r, 0), n_nodes - 1);
    atomicAdd(deg + r, 1);           // no return use -> REDG
}

// ---------------------------------------------------------------------------
// 3) exclusive prefix scan over 50K counts (single block, 1024 threads)
//    chunk=52 -> int4-aligned contiguous ranges per thread
// ---------------------------------------------------------------------------
#define CHUNK 52

__global__ void scan_kernel(const int* __restrict__ deg,
                            int* __restrict__ rowstart,
                            int* __restrict__ writeptr, int n) {
    __shared__ int ssum[1024];
    int t = threadIdx.x;
    int lo = t * CHUNK;

    int local = 0;
    if (lo < n) {
        int hi = min(n, lo + CHUNK);
        if (hi == lo + CHUNK) {
            const int4* p = (const int4*)(deg + lo);
#pragma unroll
            for (int j = 0; j < CHUNK / 4; j++) {
                int4 v = p[j];
                local += v.x + v.y + v.z + v.w;
            }
        } else {
            for (int i = lo; i < hi; i++) local += deg[i];
        }
    }

    ssum[t] = local;
    __syncthreads();
    for (int off = 1; off < 1024; off <<= 1) {
        int v = (t >= off) ? ssum[t - off] : 0;
        __syncthreads();
        ssum[t] += v;
        __syncthreads();
    }
    int start = ssum[t] - local;   // exclusive prefix of this thread's chunk

    if (lo < n) {
        int hi = min(n, lo + CHUNK);
        if (hi == lo + CHUNK) {
            const int4* p = (const int4*)(deg + lo);
            int4* rs = (int4*)(rowstart + lo);
            int4* wp = (int4*)(writeptr + lo);
#pragma unroll
            for (int j = 0; j < CHUNK / 4; j++) {
                int4 v = p[j];
                int4 o;
                o.x = start; start += v.x;
                o.y = start; start += v.y;
                o.z = start; start += v.z;
                o.w = start; start += v.w;
                rs[j] = o;
                wp[j] = o;
            }
        } else {
            for (int i = lo; i < hi; i++) {
                rowstart[i] = start;
                writeptr[i] = start;
                start += deg[i];
            }
        }
    }
}

// ---------------------------------------------------------------------------
// 4) scatter edges into receiver buckets, computing the edge weight
// ---------------------------------------------------------------------------
__global__ void scatter_kernel(const int* __restrict__ ei,
                               const float* __restrict__ elen,
                               const float* __restrict__ log_scale_p,
                               const float* __restrict__ fw_p,
                               const float* __restrict__ fb_p,
                               int* __restrict__ writeptr,
                               uint2* __restrict__ rec,
                               int E, int n_nodes) {
    int e = blockIdx.x * blockDim.x + threadIdx.x;
    if (e >= E) return;
    int s = ei[e];
    int r = ei[E + e];
    s = min(max(s, 0), n_nodes - 1);
    r = min(max(r, 0), n_nodes - 1);
    float len = elen[e];

    float scale = expf(log_scale_p[0]);
    float t = fmaxf(len / (scale + 1e-6f), 0.f);
    float d = expf(-t * t);
    float g = 1.f / (1.f + expf(-(len * fw_p[0] + fb_p[0])));
    float w = d * g;
    if (!(w > -3.0e38f && w < 3.0e38f)) w = 0.f;  // nan_to_num

    int pos = atomicAdd(writeptr + r, 1);
    rec[pos] = make_uint2((unsigned)s, __float_as_uint(w));
}

// ---------------------------------------------------------------------------
// 5) race-free gather (fp16 x): warp per node, lane handles 4 halves (8B).
//    8-edge unroll; fp32 accumulate; writes normalized agg.
// ---------------------------------------------------------------------------
__global__ void gather_kernel(const __half* __restrict__ xh,
                              const uint2* __restrict__ rec,
                              const int* __restrict__ rowstart,
                              const int* __restrict__ deg,
                              float* __restrict__ agg, int n_nodes) {
    int wid  = (blockIdx.x * blockDim.x + threadIdx.x) >> 5;
    int lane = threadIdx.x & 31;
    if (wid >= n_nodes) return;

    int base = rowstart[wid];
    int d    = deg[wid];
    float4 acc = make_float4(0.f, 0.f, 0.f, 0.f);

    for (int j0 = 0; j0 < d; j0 += 32) {
        int n = min(32, d - j0);
        uint2 rv = make_uint2(0u, 0u);
        if (lane < n) rv = rec[base + j0 + lane];

        int k = 0;
        for (; k + 8 <= n; k += 8) {
            int   si[8];
            float wi[8];
#pragma unroll
            for (int u = 0; u < 8; u++) {
                si[u] = __shfl_sync(0xffffffffu, (int)rv.x, k + u);
                wi[u] = __uint_as_float(__shfl_sync(0xffffffffu, rv.y, k + u));
            }
            uint2 hv[8];
#pragma unroll
            for (int u = 0; u < 8; u++) {
                hv[u] = ((const uint2*)(xh + (size_t)si[u] * FEAT))[lane];
            }
#pragma unroll
            for (int u = 0; u < 8; u++) {
                float2 f0 = __half22float2(*(__half2*)&hv[u].x);
                float2 f1 = __half22float2(*(__half2*)&hv[u].y);
                acc.x = fmaf(wi[u], f0.x, acc.x);
                acc.y = fmaf(wi[u], f0.y, acc.y);
                acc.z = fmaf(wi[u], f1.x, acc.z);
                acc.w = fmaf(wi[u], f1.y, acc.w);
            }
        }
        for (; k < n; k++) {
            int   s0 = __shfl_sync(0xffffffffu, (int)rv.x, k);
            float w0 = __uint_as_float(__shfl_sync(0xffffffffu, rv.y, k));
            uint2 hv = ((const uint2*)(xh + (size_t)s0 * FEAT))[lane];
            float2 f0 = __half22float2(*(__half2*)&hv.x);
            float2 f1 = __half22float2(*(__half2*)&hv.y);
            acc.x = fmaf(w0, f0.x, acc.x);
            acc.y = fmaf(w0, f0.y, acc.y);
            acc.z = fmaf(w0, f1.x, acc.z);
            acc.w = fmaf(w0, f1.y, acc.w);
        }
    }

    float inv = 1.f / fmaxf((float)d, 1.f);
    ((float4*)(agg + (size_t)wid * FEAT))[lane] =
        make_float4(acc.x * inv, acc.y * inv, acc.z * inv, acc.w * inv);
}

// ---------------------------------------------------------------------------
// 6) out = x + agg @ W_mix   — packed f32x2 FMA (FFMA2) inner loop
// ---------------------------------------------------------------------------
#define BM 64

__global__ void gemm_kernel(const float* __restrict__ x,
                            const float* __restrict__ W,
                            const float* __restrict__ agg,
                            float* __restrict__ out,
                            int n_nodes) {
    extern __shared__ float sm[];
    float* Ws = sm;                  // 128*128
    float* As = sm + FEAT * FEAT;    // BM*128

    int tid = threadIdx.x;
    int row0 = blockIdx.x * BM;

    for (int i = tid; i < FEAT * FEAT / 4; i += 256) {
        ((float4*)Ws)[i] = ((const float4*)W)[i];
    }
    for (int i = tid; i < BM * FEAT / 4; i += 256) {
        int r = i / (FEAT / 4);
        int c = i % (FEAT / 4);
        int row = row0 + r;
        float4 v = make_float4(0.f, 0.f, 0.f, 0.f);
        if (row < n_nodes) {
            v = ((const float4*)(agg + (size_t)row * FEAT))[c];
        }
        ((float4*)(As + r * FEAT))[c] = v;
    }
    __syncthreads();

    int tx = tid & 31;   // cols [tx*4, tx*4+3]
    int ty = tid >> 5;   // rows [ty*8, ty*8+7]

    unsigned long long acc01[8], acc23[8];
#pragma unroll
    for (int r = 0; r < 8; r++) { acc01[r] = 0ull; acc23[r] = 0ull; }

#pragma unroll 4
    for (int k = 0; k < FEAT; k++) {
        // w row k, cols tx*4..tx*4+3 as two packed f32x2 (16B aligned)
        ulonglong2 w2 = *(const ulonglong2*)(Ws + k * FEAT + tx * 4);
#pragma unroll
        for (int r = 0; r < 8; r++) {
            float a = As[(ty * 8 + r) * FEAT + k];   // warp-uniform broadcast
            unsigned long long aa;
            asm("mov.b64 %0, {%1, %1};" : "=l"(aa) : "r"(__float_as_uint(a)));
            asm("fma.rn.f32x2 %0, %1, %2, %0;" : "+l"(acc01[r]) : "l"(aa), "l"(w2.x));
            asm("fma.rn.f32x2 %0, %1, %2, %0;" : "+l"(acc23[r]) : "l"(aa), "l"(w2.y));
        }
    }

#pragma unroll
    for (int r = 0; r < 8; r++) {
        int row = row0 + ty * 8 + r;
        if (row < n_nodes) {
            unsigned c0u, c1u, c2u, c3u;
            asm("mov.b64 {%0, %1}, %2;" : "=r"(c0u), "=r"(c1u) : "l"(acc01[r]));
            asm("mov.b64 {%0, %1}, %2;" : "=r"(c2u), "=r"(c3u) : "l"(acc23[r]));
            float4 xv = ((const float4*)(x + (size_t)row * FEAT))[tx];
            float4 o = make_float4(__uint_as_float(c0u) + xv.x,
                                   __uint_as_float(c1u) + xv.y,
                                   __uint_as_float(c2u) + xv.z,
                                   __uint_as_float(c3u) + xv.w);
            ((float4*)(out + (size_t)row * FEAT))[tx] = o;
        }
    }
}

// ---------------------------------------------------------------------------
extern "C" void kernel_launch(void* const* d_in, const int* in_sizes, int n_in,
                              void* d_out, int out_size) {
    const float* x    = (const float*)d_in[0];
    const int*   ei   = (const int*)d_in[1];
    const float* elen = (const float*)d_in[2];
    const float* W    = (const float*)d_in[3];
    const float* lsc  = (const float*)d_in[4];
    const float* fw   = (const float*)d_in[5];
    const float* fb   = (const float*)d_in[6];
    float* out = (float*)d_out;

    int n_nodes = in_sizes[0] / FEAT;
    int E       = in_sizes[2];
    if (E > MAX_EDGES) E = MAX_EDGES;

    float*  agg;      cudaGetSymbolAddress((void**)&agg, g_agg);
    __half* xh;       cudaGetSymbolAddress((void**)&xh, g_xh);
    int*    deg;      cudaGetSymbolAddress((void**)&deg, g_deg);
    int*    rowstart; cudaGetSymbolAddress((void**)&rowstart, g_rowstart);
    int*    writeptr; cudaGetSymbolAddress((void**)&writeptr, g_writeptr);
    uint2*  rec;      cudaGetSymbolAddress((void**)&rec, g_rec);

    // 0) x -> fp16
    {
        int n8 = n_nodes * FEAT / 8;
        convert_kernel<<<(n8 + 255) / 256, 256>>>(x, xh, n8);
    }

    // 1) zero degree counters
    zero_kernel<<<(n_nodes + 255) / 256, 256>>>(deg, n_nodes);

    // 2) receiver histogram
    hist_kernel<<<(E + 255) / 256, 256>>>(ei, deg, E, n_nodes);

    // 3) prefix scan -> rowstart / writeptr
    scan_kernel<<<1, 1024>>>(deg, rowstart, writeptr, n_nodes);

    // 4) bucket scatter with weight computation
    scatter_kernel<<<(E + 255) / 256, 256>>>(ei, elen, lsc, fw, fb,
                                             writeptr, rec, E, n_nodes);

    // 5) race-free per-node gather (warp per node)
    {
        long long total = (long long)n_nodes * 32;
        int blocks = (int)((total + 255) / 256);
        gather_kernel<<<blocks, 256>>>(xh, rec, rowstart, deg, agg, n_nodes);
    }

    // 6) GEMM + residual
    {
        int smem = (FEAT * FEAT + BM * FEAT) * (int)sizeof(float);  // 96 KB
        cudaFuncSetAttribute(gemm_kernel,
                             cudaFuncAttributeMaxDynamicSharedMemorySize, smem);
        gemm_kernel<<<(n_nodes + BM - 1) / BM, 256, smem>>>(x, W, agg, out,
                                                            n_nodes);
    }
}

// round 7
// speedup vs baseline: 1.7777x; 1.1199x over previous
#include <cuda_runtime.h>
#include <cuda_fp16.h>
#include <math.h>

#define MAX_NODES 50000
#define MAX_EDGES 1500000
#define FEAT 128
#define SCAN_BLK 256
#define MAX_SCAN_BLOCKS 256   // ceil(50000/256)=196

// Scratch (device globals; allocation-free rule)
__device__ float  g_agg[MAX_NODES * FEAT];
__device__ __half g_xh[MAX_NODES * FEAT];     // fp16 copy of x
__device__ int    g_deg[MAX_NODES];
__device__ int    g_rowstart[MAX_NODES];
__device__ int    g_writeptr[MAX_NODES];
__device__ int    g_blocksum[MAX_SCAN_BLOCKS];
__device__ uint2  g_rec[MAX_EDGES];           // {sender, weight-bits}

// ---------------------------------------------------------------------------
// 0) convert x -> fp16 (8 floats -> 8 halves per thread, 16B stores)
// ---------------------------------------------------------------------------
__global__ void convert_kernel(const float* __restrict__ x,
                               __half* __restrict__ xh, int n8) {
    int i = blockIdx.x * blockDim.x + threadIdx.x;
    if (i >= n8) return;
    const float4* x4 = (const float4*)x;
    float4 a = x4[2 * i];
    float4 b = x4[2 * i + 1];
    __half2 h0 = __floats2half2_rn(a.x, a.y);
    __half2 h1 = __floats2half2_rn(a.z, a.w);
    __half2 h2 = __floats2half2_rn(b.x, b.y);
    __half2 h3 = __floats2half2_rn(b.z, b.w);
    uint4 o;
    o.x = *(unsigned*)&h0; o.y = *(unsigned*)&h1;
    o.z = *(unsigned*)&h2; o.w = *(unsigned*)&h3;
    ((uint4*)xh)[i] = o;
}

// ---------------------------------------------------------------------------
// 1) zero the degree counters
// ---------------------------------------------------------------------------
__global__ void zero_kernel(int* __restrict__ deg, int n) {
    int i = blockIdx.x * blockDim.x + threadIdx.x;
    if (i < n) deg[i] = 0;
}

// ---------------------------------------------------------------------------
// 2) histogram of receivers
// ---------------------------------------------------------------------------
__global__ void hist_kernel(const int* __restrict__ ei, int* __restrict__ deg,
                            int E, int n_nodes) {
    int e = blockIdx.x * blockDim.x + threadIdx.x;
    if (e >= E) return;
    int r = ei[E + e];
    r = min(max(r, 0), n_nodes - 1);
    atomicAdd(deg + r, 1);           // no return use -> REDG
}

// ---------------------------------------------------------------------------
// 3) decoupled scan. ALL cross-warp shfl steps run with the FULL warp active
//    (lanes >= 8 carry identity 0) so the 0xffffffff mask is legal.
// ---------------------------------------------------------------------------
__device__ __forceinline__ int warp_incl_scan(int v, int lane) {
#pragma unroll
    for (int off = 1; off < 32; off <<= 1) {
        int u = __shfl_up_sync(0xffffffffu, v, off);
        if (lane >= off) v += u;
    }
    return v;
}

__global__ void scan_reduce_kernel(const int* __restrict__ deg,
                                   int* __restrict__ blocksum, int n) {
    __shared__ int warpsum[SCAN_BLK / 32];
    int t = threadIdx.x;
    int idx = blockIdx.x * SCAN_BLK + t;
    int v = (idx < n) ? deg[idx] : 0;
#pragma unroll
    for (int off = 16; off > 0; off >>= 1)
        v += __shfl_down_sync(0xffffffffu, v, off);
    if ((t & 31) == 0) warpsum[t >> 5] = v;
    __syncthreads();
    if (t < 32) {   // full warp active
        int s = (t < SCAN_BLK / 32) ? warpsum[t] : 0;
#pragma unroll
        for (int off = 16; off > 0; off >>= 1)
            s += __shfl_down_sync(0xffffffffu, s, off);
        if (t == 0) blocksum[blockIdx.x] = s;
    }
}

__global__ void scan_top_kernel(int* __restrict__ blocksum, int nb) {
    // single block of 256 threads; nb <= 256
    __shared__ int sh[SCAN_BLK / 32];
    int t = threadIdx.x;
    int lane = t & 31;
    int w = t >> 5;
    int v = (t < nb) ? blocksum[t] : 0;
    int incl = warp_incl_scan(v, lane);          // all 256 threads active
    if (lane == 31) sh[w] = incl;
    __syncthreads();
    if (t < 32) {   // full warp active
        int s = (t < SCAN_BLK / 32) ? sh[t] : 0;
        int si = warp_incl_scan(s, t);
        if (t < SCAN_BLK / 32) sh[t] = si - s;   // exclusive warp offsets
    }
    __syncthreads();
    if (t < nb) blocksum[t] = incl - v + sh[w];  // exclusive prefix
}

__global__ void scan_final_kernel(const int* __restrict__ deg,
                                  const int* __restrict__ blocksum,
                                  int* __restrict__ rowstart,
                                  int* __restrict__ writeptr, int n) {
    __shared__ int sh[SCAN_BLK / 32];
    int t = threadIdx.x;
    int lane = t & 31;
    int w = t >> 5;
    int idx = blockIdx.x * SCAN_BLK + t;
    int v = (idx < n) ? deg[idx] : 0;
    int incl = warp_incl_scan(v, lane);          // all 256 threads active
    if (lane == 31) sh[w] = incl;
    __syncthreads();
    if (t < 32) {   // full warp active
        int s = (t < SCAN_BLK / 32) ? sh[t] : 0;
        int si = warp_incl_scan(s, t);
        if (t < SCAN_BLK / 32) sh[t] = si - s;
    }
    __syncthreads();
    if (idx < n) {
        int start = blocksum[blockIdx.x] + sh[w] + incl - v;
        rowstart[idx] = start;
        writeptr[idx] = start;
    }
}

// ---------------------------------------------------------------------------
// 4) scatter edges into receiver buckets, computing the edge weight
// ---------------------------------------------------------------------------
__global__ void scatter_kernel(const int* __restrict__ ei,
                               const float* __restrict__ elen,
                               const float* __restrict__ log_scale_p,
                               const float* __restrict__ fw_p,
                               const float* __restrict__ fb_p,
                               int* __restrict__ writeptr,
                               uint2* __restrict__ rec,
                               int E, int n_nodes) {
    int e = blockIdx.x * blockDim.x + threadIdx.x;
    if (e >= E) return;
    int s = ei[e];
    int r = ei[E + e];
    s = min(max(s, 0), n_nodes - 1);
    r = min(max(r, 0), n_nodes - 1);
    float len = elen[e];

    float scale = expf(log_scale_p[0]);
    float t = fmaxf(len / (scale + 1e-6f), 0.f);
    float d = expf(-t * t);
    float g = 1.f / (1.f + expf(-(len * fw_p[0] + fb_p[0])));
    float w = d * g;
    if (!(w > -3.0e38f && w < 3.0e38f)) w = 0.f;  // nan_to_num

    int pos = atomicAdd(writeptr + r, 1);
    rec[pos] = make_uint2((unsigned)s, __float_as_uint(w));
}

// ---------------------------------------------------------------------------
// 5) race-free gather (fp16 x): warp per node, lane handles 4 halves (8B).
//    8-edge unroll; fp32 accumulate; writes normalized agg.
// ---------------------------------------------------------------------------
__global__ void gather_kernel(const __half* __restrict__ xh,
                              const uint2* __restrict__ rec,
                              const int* __restrict__ rowstart,
                              const int* __restrict__ deg,
                              float* __restrict__ agg, int n_nodes) {
    int wid  = (blockIdx.x * blockDim.x + threadIdx.x) >> 5;
    int lane = threadIdx.x & 31;
    if (wid >= n_nodes) return;

    int base = rowstart[wid];
    int d    = deg[wid];
    float4 acc = make_float4(0.f, 0.f, 0.f, 0.f);

    for (int j0 = 0; j0 < d; j0 += 32) {
        int n = min(32, d - j0);
        uint2 rv = make_uint2(0u, 0u);
        if (lane < n) rv = rec[base + j0 + lane];

        int k = 0;
        for (; k + 8 <= n; k += 8) {
            int   si[8];
            float wi[8];
#pragma unroll
            for (int u = 0; u < 8; u++) {
                si[u] = __shfl_sync(0xffffffffu, (int)rv.x, k + u);
                wi[u] = __uint_as_float(__shfl_sync(0xffffffffu, rv.y, k + u));
            }
            uint2 hv[8];
#pragma unroll
            for (int u = 0; u < 8; u++) {
                hv[u] = ((const uint2*)(xh + (size_t)si[u] * FEAT))[lane];
            }
#pragma unroll
            for (int u = 0; u < 8; u++) {
                float2 f0 = __half22float2(*(__half2*)&hv[u].x);
                float2 f1 = __half22float2(*(__half2*)&hv[u].y);
                acc.x = fmaf(wi[u], f0.x, acc.x);
                acc.y = fmaf(wi[u], f0.y, acc.y);
                acc.z = fmaf(wi[u], f1.x, acc.z);
                acc.w = fmaf(wi[u], f1.y, acc.w);
            }
        }
        for (; k < n; k++) {
            int   s0 = __shfl_sync(0xffffffffu, (int)rv.x, k);
            float w0 = __uint_as_float(__shfl_sync(0xffffffffu, rv.y, k));
            uint2 hv = ((const uint2*)(xh + (size_t)s0 * FEAT))[lane];
            float2 f0 = __half22float2(*(__half2*)&hv.x);
            float2 f1 = __half22float2(*(__half2*)&hv.y);
            acc.x = fmaf(w0, f0.x, acc.x);
            acc.y = fmaf(w0, f0.y, acc.y);
            acc.z = fmaf(w0, f1.x, acc.z);
            acc.w = fmaf(w0, f1.y, acc.w);
        }
    }

    float inv = 1.f / fmaxf((float)d, 1.f);
    ((float4*)(agg + (size_t)wid * FEAT))[lane] =
        make_float4(acc.x * inv, acc.y * inv, acc.z * inv, acc.w * inv);
}

// ---------------------------------------------------------------------------
// 6) out = x + agg @ W_mix   — packed f32x2 FMA (FFMA2) inner loop
// ---------------------------------------------------------------------------
#define BM 64

__global__ void gemm_kernel(const float* __restrict__ x,
                            const float* __restrict__ W,
                            const float* __restrict__ agg,
                            float* __restrict__ out,
                            int n_nodes) {
    extern __shared__ float sm[];
    float* Ws = sm;                  // 128*128
    float* As = sm + FEAT * FEAT;    // BM*128

    int tid = threadIdx.x;
    int row0 = blockIdx.x * BM;

    for (int i = tid; i < FEAT * FEAT / 4; i += 256) {
        ((float4*)Ws)[i] = ((const float4*)W)[i];
    }
    for (int i = tid; i < BM * FEAT / 4; i += 256) {
        int r = i / (FEAT / 4);
        int c = i % (FEAT / 4);
        int row = row0 + r;
        float4 v = make_float4(0.f, 0.f, 0.f, 0.f);
        if (row < n_nodes) {
            v = ((const float4*)(agg + (size_t)row * FEAT))[c];
        }
        ((float4*)(As + r * FEAT))[c] = v;
    }
    __syncthreads();

    int tx = tid & 31;   // cols [tx*4, tx*4+3]
    int ty = tid >> 5;   // rows [ty*8, ty*8+7]

    unsigned long long acc01[8], acc23[8];
#pragma unroll
    for (int r = 0; r < 8; r++) { acc01[r] = 0ull; acc23[r] = 0ull; }

#pragma unroll 4
    for (int k = 0; k < FEAT; k++) {
        ulonglong2 w2 = *(const ulonglong2*)(Ws + k * FEAT + tx * 4);
#pragma unroll
        for (int r = 0; r < 8; r++) {
            float a = As[(ty * 8 + r) * FEAT + k];   // warp-uniform broadcast
            unsigned long long aa;
            asm("mov.b64 %0, {%1, %1};" : "=l"(aa) : "r"(__float_as_uint(a)));
            asm("fma.rn.f32x2 %0, %1, %2, %0;" : "+l"(acc01[r]) : "l"(aa), "l"(w2.x));
            asm("fma.rn.f32x2 %0, %1, %2, %0;" : "+l"(acc23[r]) : "l"(aa), "l"(w2.y));
        }
    }

#pragma unroll
    for (int r = 0; r < 8; r++) {
        int row = row0 + ty * 8 + r;
        if (row < n_nodes) {
            unsigned c0u, c1u, c2u, c3u;
            asm("mov.b64 {%0, %1}, %2;" : "=r"(c0u), "=r"(c1u) : "l"(acc01[r]));
            asm("mov.b64 {%0, %1}, %2;" : "=r"(c2u), "=r"(c3u) : "l"(acc23[r]));
            float4 xv = ((const float4*)(x + (size_t)row * FEAT))[tx];
            float4 o = make_float4(__uint_as_float(c0u) + xv.x,
                                   __uint_as_float(c1u) + xv.y,
                                   __uint_as_float(c2u) + xv.z,
                                   __uint_as_float(c3u) + xv.w);
            ((float4*)(out + (size_t)row * FEAT))[tx] = o;
        }
    }
}

// ---------------------------------------------------------------------------
extern "C" void kernel_launch(void* const* d_in, const int* in_sizes, int n_in,
                              void* d_out, int out_size) {
    const float* x    = (const float*)d_in[0];
    const int*   ei   = (const int*)d_in[1];
    const float* elen = (const float*)d_in[2];
    const float* W    = (const float*)d_in[3];
    const float* lsc  = (const float*)d_in[4];
    const float* fw   = (const float*)d_in[5];
    const float* fb   = (const float*)d_in[6];
    float* out = (float*)d_out;

    int n_nodes = in_sizes[0] / FEAT;
    int E       = in_sizes[2];
    if (E > MAX_EDGES) E = MAX_EDGES;

    float*  agg;      cudaGetSymbolAddress((void**)&agg, g_agg);
    __half* xh;       cudaGetSymbolAddress((void**)&xh, g_xh);
    int*    deg;      cudaGetSymbolAddress((void**)&deg, g_deg);
    int*    rowstart; cudaGetSymbolAddress((void**)&rowstart, g_rowstart);
    int*    writeptr; cudaGetSymbolAddress((void**)&writeptr, g_writeptr);
    int*    blocksum; cudaGetSymbolAddress((void**)&blocksum, g_blocksum);
    uint2*  rec;      cudaGetSymbolAddress((void**)&rec, g_rec);

    // 0) x -> fp16
    {
        int n8 = n_nodes * FEAT / 8;
        convert_kernel<<<(n8 + 255) / 256, 256>>>(x, xh, n8);
    }

    // 1) zero degree counters
    zero_kernel<<<(n_nodes + 255) / 256, 256>>>(deg, n_nodes);

    // 2) receiver histogram
    hist_kernel<<<(E + 255) / 256, 256>>>(ei, deg, E, n_nodes);

    // 3) decoupled prefix scan -> rowstart / writeptr
    {
        int nb = (n_nodes + SCAN_BLK - 1) / SCAN_BLK;   // 196
        scan_reduce_kernel<<<nb, SCAN_BLK>>>(deg, blocksum, n_nodes);
        scan_top_kernel<<<1, SCAN_BLK>>>(blocksum, nb);
        scan_final_kernel<<<nb, SCAN_BLK>>>(deg, blocksum, rowstart,
                                            writeptr, n_nodes);
    }

    // 4) bucket scatter with weight computation
    scatter_kernel<<<(E + 255) / 256, 256>>>(ei, elen, lsc, fw, fb,
                                             writeptr, rec, E, n_nodes);

    // 5) race-free per-node gather (warp per node)
    {
        long long total = (long long)n_nodes * 32;
        int blocks = (int)((total + 255) / 256);
        gather_kernel<<<blocks, 256>>>(xh, rec, rowstart, deg, agg, n_nodes);
    }

    // 6) GEMM + residual
    {
        int smem = (FEAT * FEAT + BM * FEAT) * (int)sizeof(float);  // 96 KB
        cudaFuncSetAttribute(gemm_kernel,
                             cudaFuncAttributeMaxDynamicSharedMemorySize, smem);
        gemm_kernel<<<(n_nodes + BM - 1) / BM, 256, smem>>>(x, W, agg, out,
                                                            n_nodes);
    }
}